// round 1
// baseline (speedup 1.0000x reference)
#include <cuda_runtime.h>

// Problem constants
#define Bn 4
#define Cc 256
#define Nn 1024
#define Hh 8
#define Dd 256
#define HD 2048   // H*D

// Scratch (device globals; no allocation allowed)
__device__ float g_Q[Bn * HD * Nn];          // [B, H*D, N]
__device__ float g_K[Bn * HD * Nn];
__device__ float g_V[Bn * HD * Nn];
__device__ float g_YP[Bn * Cc * Nn];         // [B, DV, N]
__device__ float g_S[(size_t)Bn * Hh * Nn * Nn];  // [B*H, N, N] logits -> probs

// ---------------------------------------------------------------------------
// Projection GEMM: O[b][m][n] = sum_c W[m][c] * X[b][c][n] + bias[m]
// Tile 128(m) x 128(n), Ktile=16, 256 threads, 8x8 per-thread microtile.
// which: 0->g_Q, 1->g_K, 2->g_V, 3->g_YP
// ---------------------------------------------------------------------------
__global__ void proj_kernel(const float* __restrict__ W,
                            const float* __restrict__ bias,
                            const float* __restrict__ X,
                            int M, int which)
{
    __shared__ float sW[16][132];   // [k][m]
    __shared__ float sX[16][132];   // [k][n]

    const int b  = blockIdx.z;
    const int m0 = blockIdx.y * 128;
    const int n0 = blockIdx.x * 128;
    const int t  = threadIdx.x;
    const int tm = t / 16;          // 0..15
    const int tn = t % 16;          // 0..15

    const float* Xb = X + (size_t)b * Cc * Nn;

    float acc[8][8];
#pragma unroll
    for (int i = 0; i < 8; i++)
#pragma unroll
        for (int j = 0; j < 8; j++) acc[i][j] = 0.f;

    for (int k0 = 0; k0 < Cc; k0 += 16) {
        // Load W tile: 128 rows(m) x 16 cols(k)
        {
            const int kk  = t % 16;
            const int mm0 = t / 16;   // 0..15
#pragma unroll
            for (int r = 0; r < 8; r++) {
                int mm = mm0 + 16 * r;
                sW[kk][mm] = W[(size_t)(m0 + mm) * Cc + (k0 + kk)];
            }
        }
        // Load X tile: 16 rows(k) x 128 cols(n)
        {
            const int mm  = t % 128;
            const int kk0 = t / 128;  // 0..1
#pragma unroll
            for (int r = 0; r < 8; r++) {
                int kk = kk0 + 2 * r;
                sX[kk][mm] = Xb[(size_t)(k0 + kk) * Nn + (n0 + mm)];
            }
        }
        __syncthreads();

#pragma unroll
        for (int kk = 0; kk < 16; kk++) {
            float a8[8], b8[8];
#pragma unroll
            for (int i = 0; i < 8; i++) a8[i] = sW[kk][tm * 8 + i];
#pragma unroll
            for (int j = 0; j < 8; j++) b8[j] = sX[kk][tn * 8 + j];
#pragma unroll
            for (int i = 0; i < 8; i++)
#pragma unroll
                for (int j = 0; j < 8; j++) acc[i][j] += a8[i] * b8[j];
        }
        __syncthreads();
    }

    float* O = (which == 0) ? g_Q : (which == 1) ? g_K : (which == 2) ? g_V : g_YP;

#pragma unroll
    for (int i = 0; i < 8; i++) {
        const int m  = m0 + tm * 8 + i;
        const float bb = bias ? bias[m] : 0.f;
#pragma unroll
        for (int j = 0; j < 8; j++) {
            const int n = n0 + tn * 8 + j;
            O[((size_t)b * M + m) * Nn + n] = acc[i][j] + bb;
        }
    }
}

// ---------------------------------------------------------------------------
// QK^T: S[bh][i][j] = sum_d Q[bh][d][i] * K[bh][d][j]
// Both operands d-major (i/j contiguous) -> coalesced 16(k) x 128 tile loads.
// ---------------------------------------------------------------------------
__global__ void qk_kernel()
{
    __shared__ float sA[16][132];   // [d][i]
    __shared__ float sB[16][132];   // [d][j]

    const int bh = blockIdx.z;
    const int i0 = blockIdx.y * 128;
    const int j0 = blockIdx.x * 128;
    const int t  = threadIdx.x;
    const int tm = t / 16;
    const int tn = t % 16;

    const float* Q  = g_Q + (size_t)bh * Dd * Nn;
    const float* Kp = g_K + (size_t)bh * Dd * Nn;
    float* S = g_S + (size_t)bh * Nn * Nn;

    float acc[8][8];
#pragma unroll
    for (int i = 0; i < 8; i++)
#pragma unroll
        for (int j = 0; j < 8; j++) acc[i][j] = 0.f;

    for (int d0 = 0; d0 < Dd; d0 += 16) {
        const int mm  = t % 128;
        const int kk0 = t / 128;   // 0..1
#pragma unroll
        for (int r = 0; r < 8; r++) {
            int kk = kk0 + 2 * r;
            sA[kk][mm] = Q [(size_t)(d0 + kk) * Nn + (i0 + mm)];
            sB[kk][mm] = Kp[(size_t)(d0 + kk) * Nn + (j0 + mm)];
        }
        __syncthreads();

#pragma unroll
        for (int kk = 0; kk < 16; kk++) {
            float a8[8], b8[8];
#pragma unroll
            for (int i = 0; i < 8; i++) a8[i] = sA[kk][tm * 8 + i];
#pragma unroll
            for (int j = 0; j < 8; j++) b8[j] = sB[kk][tn * 8 + j];
#pragma unroll
            for (int i = 0; i < 8; i++)
#pragma unroll
                for (int j = 0; j < 8; j++) acc[i][j] += a8[i] * b8[j];
        }
        __syncthreads();
    }

#pragma unroll
    for (int i = 0; i < 8; i++) {
        const int gi = i0 + tm * 8 + i;
#pragma unroll
        for (int j = 0; j < 8; j++) {
            S[(size_t)gi * Nn + (j0 + tn * 8 + j)] = acc[i][j];
        }
    }
}

// ---------------------------------------------------------------------------
// Row softmax over S (rows of length Nn=1024). One block (256 thr) per row.
// ---------------------------------------------------------------------------
__global__ void softmax_kernel()
{
    const size_t row = blockIdx.x;
    float* p = g_S + row * (size_t)Nn;
    const int t = threadIdx.x;

    float v[4];
    float m = -1e30f;
#pragma unroll
    for (int r = 0; r < 4; r++) {
        v[r] = p[t + 256 * r];
        m = fmaxf(m, v[r]);
    }
#pragma unroll
    for (int o = 16; o > 0; o >>= 1) m = fmaxf(m, __shfl_xor_sync(0xffffffffu, m, o));

    __shared__ float sred[8];
    if ((t & 31) == 0) sred[t >> 5] = m;
    __syncthreads();
    if (t == 0) {
        float mm = sred[0];
#pragma unroll
        for (int i = 1; i < 8; i++) mm = fmaxf(mm, sred[i]);
        sred[0] = mm;
    }
    __syncthreads();
    const float bm = sred[0];
    __syncthreads();

    float s = 0.f;
#pragma unroll
    for (int r = 0; r < 4; r++) {
        v[r] = __expf(v[r] - bm);
        s += v[r];
    }
#pragma unroll
    for (int o = 16; o > 0; o >>= 1) s += __shfl_xor_sync(0xffffffffu, s, o);
    if ((t & 31) == 0) sred[t >> 5] = s;
    __syncthreads();
    if (t == 0) {
        float ss = sred[0];
#pragma unroll
        for (int i = 1; i < 8; i++) ss += sred[i];
        sred[0] = ss;
    }
    __syncthreads();
    const float inv = 1.f / sred[0];

#pragma unroll
    for (int r = 0; r < 4; r++) p[t + 256 * r] = v[r] * inv;
}

// ---------------------------------------------------------------------------
// out[b][h*Dd+d][i] = (gamma[h] * sum_j V[bh][d][j]*P[bh][i][j] + yp[b][d][i])
//                     / (1 + gamma[h])
// C = V * P^T : M=256(d), N=1024(i), K=1024(j). Tile 128x128, Ktile=16.
// ---------------------------------------------------------------------------
__global__ void av_kernel(const float* __restrict__ gamma, float* __restrict__ out)
{
    __shared__ float sA[16][132];   // [j][d]
    __shared__ float sB[16][132];   // [j][i]

    const int bh = blockIdx.z;
    const int b  = bh / Hh;
    const int h  = bh % Hh;
    const int d0 = blockIdx.y * 128;
    const int i0 = blockIdx.x * 128;
    const int t  = threadIdx.x;
    const int tm = t / 16;
    const int tn = t % 16;

    const float* V = g_V + (size_t)bh * Dd * Nn;
    const float* P = g_S + (size_t)bh * Nn * Nn;

    float acc[8][8];
#pragma unroll
    for (int i = 0; i < 8; i++)
#pragma unroll
        for (int j = 0; j < 8; j++) acc[i][j] = 0.f;

    for (int j0 = 0; j0 < Nn; j0 += 16) {
        const int kk  = t % 16;
        const int mm0 = t / 16;  // 0..15
#pragma unroll
        for (int r = 0; r < 8; r++) {
            int mm = mm0 + 16 * r;
            sA[kk][mm] = V[(size_t)(d0 + mm) * Nn + (j0 + kk)];
            sB[kk][mm] = P[(size_t)(i0 + mm) * Nn + (j0 + kk)];
        }
        __syncthreads();

#pragma unroll
        for (int kk2 = 0; kk2 < 16; kk2++) {
            float a8[8], b8[8];
#pragma unroll
            for (int i = 0; i < 8; i++) a8[i] = sA[kk2][tm * 8 + i];
#pragma unroll
            for (int j = 0; j < 8; j++) b8[j] = sB[kk2][tn * 8 + j];
#pragma unroll
            for (int i = 0; i < 8; i++)
#pragma unroll
                for (int j = 0; j < 8; j++) acc[i][j] += a8[i] * b8[j];
        }
        __syncthreads();
    }

    const float g   = gamma[h];
    const float inv = 1.f / (1.f + g);

#pragma unroll
    for (int di = 0; di < 8; di++) {
        const int d = d0 + tm * 8 + di;
#pragma unroll
        for (int ii = 0; ii < 8; ii++) {
            const int i = i0 + tn * 8 + ii;
            const float yp = g_YP[((size_t)b * Cc + d) * Nn + i];
            out[((size_t)b * HD + (size_t)h * Dd + d) * Nn + i] =
                (g * acc[di][ii] + yp) * inv;
        }
    }
}

// ---------------------------------------------------------------------------
extern "C" void kernel_launch(void* const* d_in, const int* in_sizes, int n_in,
                              void* d_out, int out_size)
{
    const float* x     = (const float*)d_in[0];
    const float* y     = (const float*)d_in[1];
    const float* Wq    = (const float*)d_in[2];
    const float* bq    = (const float*)d_in[3];
    const float* Wk    = (const float*)d_in[4];
    const float* bk    = (const float*)d_in[5];
    const float* Wv    = (const float*)d_in[6];
    const float* bv    = (const float*)d_in[7];
    const float* Wp    = (const float*)d_in[8];
    const float* gamma = (const float*)d_in[9];
    float* out = (float*)d_out;

    dim3 blk(256);

    // Projections: Q, K from x; V, YP from y
    proj_kernel<<<dim3(Nn / 128, HD / 128, Bn), blk>>>(Wq, bq, x, HD, 0);
    proj_kernel<<<dim3(Nn / 128, HD / 128, Bn), blk>>>(Wk, bk, x, HD, 1);
    proj_kernel<<<dim3(Nn / 128, HD / 128, Bn), blk>>>(Wv, bv, y, HD, 2);
    proj_kernel<<<dim3(Nn / 128, Cc / 128, Bn), blk>>>(Wp, nullptr, y, Cc, 3);

    // Attention logits, softmax, output + epilogue
    qk_kernel<<<dim3(Nn / 128, Nn / 128, Bn * Hh), blk>>>();
    softmax_kernel<<<Bn * Hh * Nn, 256>>>();
    av_kernel<<<dim3(Nn / 128, Dd / 128, Bn * Hh), blk>>>(gamma, out);
}

// round 4
// speedup vs baseline: 2.9201x; 2.9201x over previous
#include <cuda_runtime.h>

#define Bn 4
#define Cc 256
#define Nn 1024
#define Hh 8
#define Dd 256
#define HD 2048   // H*D

// Scratch (device globals; no allocation allowed)
__device__ float g_Q[Bn * HD * Nn];
__device__ float g_K[Bn * HD * Nn];
__device__ float g_V[Bn * HD * Nn];
__device__ float g_YP[Bn * Cc * Nn];
__device__ float g_S[(size_t)Bn * Hh * Nn * Nn];

// SMEM strides (in 32-bit words), chosen for conflict-free fragment LDS
#define STR_MK 20    // [m][k] / [n][k] tiles: 128 rows x (16+4)
#define STR_KN 136   // [k][m] / [k][n] tiles: 16 rows x (128+8)

// ---------------------------------------------------------------------------
__device__ __forceinline__ unsigned f2tf32(float f) {
    unsigned u;
    asm("cvt.rna.tf32.f32 %0, %1;" : "=r"(u) : "f"(f));
    return u;
}

__device__ __forceinline__ void mma8(float* c, const unsigned* a, const unsigned* b) {
    asm volatile(
        "mma.sync.aligned.m16n8k8.row.col.f32.tf32.tf32.f32 "
        "{%0,%1,%2,%3},{%4,%5,%6,%7},{%8,%9},{%0,%1,%2,%3};\n"
        : "+f"(c[0]), "+f"(c[1]), "+f"(c[2]), "+f"(c[3])
        : "r"(a[0]), "r"(a[1]), "r"(a[2]), "r"(a[3]), "r"(b[0]), "r"(b[1]));
}

// ---- global tile loaders (to registers) -----------------------------------
// 16 rows x 128 contiguous cols
__device__ __forceinline__ void load_16x128(const float* base, int ld, int r0, int c0,
                                            int t, float4 v[2]) {
#pragma unroll
    for (int r = 0; r < 2; r++) {
        int q = t + 256 * r;
        int row = q >> 5, c4 = q & 31;
        v[r] = *reinterpret_cast<const float4*>(base + (size_t)(r0 + row) * ld + c0 + c4 * 4);
    }
}
// 128 rows x 16 contiguous cols
__device__ __forceinline__ void load_128x16(const float* base, int ld, int r0, int c0,
                                            int t, float4 v[2]) {
#pragma unroll
    for (int r = 0; r < 2; r++) {
        int q = t + 256 * r;
        int row = q >> 2, c4 = q & 3;
        v[r] = *reinterpret_cast<const float4*>(base + (size_t)(r0 + row) * ld + c0 + c4 * 4);
    }
}
// ---- SMEM stores (convert to tf32 bits) -----------------------------------
__device__ __forceinline__ void store_16x128(unsigned* buf, int t, const float4 v[2]) {
#pragma unroll
    for (int r = 0; r < 2; r++) {
        int q = t + 256 * r;
        int row = q >> 5, c4 = q & 31;
        unsigned* p = buf + row * STR_KN + c4 * 4;
        *reinterpret_cast<uint2*>(p)     = make_uint2(f2tf32(v[r].x), f2tf32(v[r].y));
        *reinterpret_cast<uint2*>(p + 2) = make_uint2(f2tf32(v[r].z), f2tf32(v[r].w));
    }
}
__device__ __forceinline__ void store_128x16(unsigned* buf, int t, const float4 v[2]) {
#pragma unroll
    for (int r = 0; r < 2; r++) {
        int q = t + 256 * r;
        int row = q >> 2, c4 = q & 3;
        *reinterpret_cast<uint4*>(buf + row * STR_MK + c4 * 4) =
            make_uint4(f2tf32(v[r].x), f2tf32(v[r].y), f2tf32(v[r].z), f2tf32(v[r].w));
    }
}

// ---- one Ktile=16 of mma over the 128x128 block tile ----------------------
// AKM: A smem is [m][k] stride 20 (else [k][m] stride 136)
// BNK: B smem is [n][k] stride 20 (else [k][n] stride 136)
template <bool AKM, bool BNK>
__device__ __forceinline__ void compute_ktile(const unsigned* As, const unsigned* Bs,
                                              float acc[2][8][4], int lane, int wm, int wn) {
    const int rA = wm * 32 + (lane >> 2);
    const int nB = wn * 64 + (lane >> 2);
    const int kq = lane & 3;
#pragma unroll
    for (int k8 = 0; k8 < 16; k8 += 8) {
        unsigned a[2][4];
#pragma unroll
        for (int f = 0; f < 2; f++) {
            int r = rA + f * 16, c = k8 + kq;
            if (AKM) {
                a[f][0] = As[r * STR_MK + c];       a[f][1] = As[(r + 8) * STR_MK + c];
                a[f][2] = As[r * STR_MK + c + 4];   a[f][3] = As[(r + 8) * STR_MK + c + 4];
            } else {
                a[f][0] = As[c * STR_KN + r];       a[f][1] = As[c * STR_KN + r + 8];
                a[f][2] = As[(c + 4) * STR_KN + r]; a[f][3] = As[(c + 4) * STR_KN + r + 8];
            }
        }
        unsigned b[8][2];
#pragma unroll
        for (int f = 0; f < 8; f++) {
            int n = nB + f * 8, k = k8 + kq;
            if (BNK) { b[f][0] = Bs[n * STR_MK + k]; b[f][1] = Bs[n * STR_MK + k + 4]; }
            else     { b[f][0] = Bs[k * STR_KN + n]; b[f][1] = Bs[(k + 4) * STR_KN + n]; }
        }
#pragma unroll
        for (int fm = 0; fm < 2; fm++)
#pragma unroll
            for (int fn = 0; fn < 8; fn++) mma8(acc[fm][fn], a[fm], b[fn]);
    }
}

// ---------------------------------------------------------------------------
// Projection: O[b][m][n] = sum_c W[m][c]*X[b][c][n] + bias[m]
// which: 0->g_Q, 1->g_K, 2->g_V, 3->g_YP
// ---------------------------------------------------------------------------
__global__ void __launch_bounds__(256) proj_t(const float* __restrict__ W,
                                              const float* __restrict__ bias,
                                              const float* __restrict__ X,
                                              int M, int which) {
    __shared__ unsigned As[2][128 * STR_MK];
    __shared__ unsigned Bs[2][16 * STR_KN];

    const int b = blockIdx.z;
    const int m0 = blockIdx.y * 128, n0 = blockIdx.x * 128;
    const int t = threadIdx.x, lane = t & 31, warp = t >> 5;
    const int wm = warp >> 1, wn = warp & 1;
    const float* Xb = X + (size_t)b * Cc * Nn;

    float acc[2][8][4];
#pragma unroll
    for (int i = 0; i < 2; i++)
#pragma unroll
        for (int j = 0; j < 8; j++)
#pragma unroll
            for (int k = 0; k < 4; k++) acc[i][j][k] = 0.f;

    float4 va[2], vb[2];
    load_128x16(W, Cc, m0, 0, t, va);
    load_16x128(Xb, Nn, 0, n0, t, vb);
    store_128x16(As[0], t, va);
    store_16x128(Bs[0], t, vb);

    const int KT = Cc / 16;
    for (int kt = 0; kt < KT; kt++) {
        __syncthreads();
        int cur = kt & 1;
        if (kt + 1 < KT) {
            load_128x16(W, Cc, m0, (kt + 1) * 16, t, va);
            load_16x128(Xb, Nn, (kt + 1) * 16, n0, t, vb);
        }
        compute_ktile<true, false>(As[cur], Bs[cur], acc, lane, wm, wn);
        if (kt + 1 < KT) {
            store_128x16(As[cur ^ 1], t, va);
            store_16x128(Bs[cur ^ 1], t, vb);
        }
    }

    float* O = (which == 0) ? g_Q : (which == 1) ? g_K : (which == 2) ? g_V : g_YP;
#pragma unroll
    for (int fm = 0; fm < 2; fm++) {
        const int m = m0 + wm * 32 + fm * 16 + (lane >> 2);
        const float b0 = bias ? bias[m] : 0.f;
        const float b1 = bias ? bias[m + 8] : 0.f;
#pragma unroll
        for (int fn = 0; fn < 8; fn++) {
            const int n = n0 + wn * 64 + fn * 8 + (lane & 3) * 2;
            float* p0 = O + ((size_t)b * M + m) * Nn + n;
            float* p1 = O + ((size_t)b * M + m + 8) * Nn + n;
            *reinterpret_cast<float2*>(p0) = make_float2(acc[fm][fn][0] + b0, acc[fm][fn][1] + b0);
            *reinterpret_cast<float2*>(p1) = make_float2(acc[fm][fn][2] + b1, acc[fm][fn][3] + b1);
        }
    }
}

// ---------------------------------------------------------------------------
// QK^T: S[bh][i][j] = sum_d Q[bh][d][i] * K[bh][d][j]
// ---------------------------------------------------------------------------
__global__ void __launch_bounds__(256) qk_t() {
    __shared__ unsigned As[2][16 * STR_KN];
    __shared__ unsigned Bs[2][16 * STR_KN];

    const int bh = blockIdx.z;
    const int i0 = blockIdx.y * 128, j0 = blockIdx.x * 128;
    const int t = threadIdx.x, lane = t & 31, warp = t >> 5;
    const int wm = warp >> 1, wn = warp & 1;

    const float* Q  = g_Q + (size_t)bh * Dd * Nn;
    const float* Kp = g_K + (size_t)bh * Dd * Nn;

    float acc[2][8][4];
#pragma unroll
    for (int i = 0; i < 2; i++)
#pragma unroll
        for (int j = 0; j < 8; j++)
#pragma unroll
            for (int k = 0; k < 4; k++) acc[i][j][k] = 0.f;

    float4 va[2], vb[2];
    load_16x128(Q, Nn, 0, i0, t, va);
    load_16x128(Kp, Nn, 0, j0, t, vb);
    store_16x128(As[0], t, va);
    store_16x128(Bs[0], t, vb);

    const int KT = Dd / 16;
    for (int kt = 0; kt < KT; kt++) {
        __syncthreads();
        int cur = kt & 1;
        if (kt + 1 < KT) {
            load_16x128(Q, Nn, (kt + 1) * 16, i0, t, va);
            load_16x128(Kp, Nn, (kt + 1) * 16, j0, t, vb);
        }
        compute_ktile<false, false>(As[cur], Bs[cur], acc, lane, wm, wn);
        if (kt + 1 < KT) {
            store_16x128(As[cur ^ 1], t, va);
            store_16x128(Bs[cur ^ 1], t, vb);
        }
    }

    float* S = g_S + (size_t)bh * Nn * Nn;
#pragma unroll
    for (int fm = 0; fm < 2; fm++) {
        const int r = i0 + wm * 32 + fm * 16 + (lane >> 2);
#pragma unroll
        for (int fn = 0; fn < 8; fn++) {
            const int c = j0 + wn * 64 + fn * 8 + (lane & 3) * 2;
            *reinterpret_cast<float2*>(&S[(size_t)r * Nn + c]) =
                make_float2(acc[fm][fn][0], acc[fm][fn][1]);
            *reinterpret_cast<float2*>(&S[(size_t)(r + 8) * Nn + c]) =
                make_float2(acc[fm][fn][2], acc[fm][fn][3]);
        }
    }
}

// ---------------------------------------------------------------------------
// Row softmax over S (rows of length Nn=1024). One block (256 thr) per row.
// ---------------------------------------------------------------------------
__global__ void softmax_kernel() {
    const size_t row = blockIdx.x;
    float* p = g_S + row * (size_t)Nn;
    const int t = threadIdx.x;

    float v[4];
    float m = -1e30f;
#pragma unroll
    for (int r = 0; r < 4; r++) {
        v[r] = p[t + 256 * r];
        m = fmaxf(m, v[r]);
    }
#pragma unroll
    for (int o = 16; o > 0; o >>= 1) m = fmaxf(m, __shfl_xor_sync(0xffffffffu, m, o));

    __shared__ float sred[8];
    if ((t & 31) == 0) sred[t >> 5] = m;
    __syncthreads();
    if (t == 0) {
        float mm = sred[0];
#pragma unroll
        for (int i = 1; i < 8; i++) mm = fmaxf(mm, sred[i]);
        sred[0] = mm;
    }
    __syncthreads();
    const float bm = sred[0];
    __syncthreads();

    float s = 0.f;
#pragma unroll
    for (int r = 0; r < 4; r++) {
        v[r] = __expf(v[r] - bm);
        s += v[r];
    }
#pragma unroll
    for (int o = 16; o > 0; o >>= 1) s += __shfl_xor_sync(0xffffffffu, s, o);
    if ((t & 31) == 0) sred[t >> 5] = s;
    __syncthreads();
    if (t == 0) {
        float ss = sred[0];
#pragma unroll
        for (int i = 1; i < 8; i++) ss += sred[i];
        sred[0] = ss;
    }
    __syncthreads();
    const float inv = 1.f / sred[0];

#pragma unroll
    for (int r = 0; r < 4; r++) p[t + 256 * r] = v[r] * inv;
}

// ---------------------------------------------------------------------------
// out = (gamma * V*P^T + yp) / (1+gamma)
// M=256(d), N=1024(i), K=1024(j)
// ---------------------------------------------------------------------------
__global__ void __launch_bounds__(256) av_t(const float* __restrict__ gamma,
                                            float* __restrict__ out) {
    __shared__ unsigned As[2][128 * STR_MK];
    __shared__ unsigned Bs[2][128 * STR_MK];

    const int bh = blockIdx.z;
    const int b = bh / Hh, h = bh % Hh;
    const int d0 = blockIdx.y * 128, i0 = blockIdx.x * 128;
    const int t = threadIdx.x, lane = t & 31, warp = t >> 5;
    const int wm = warp >> 1, wn = warp & 1;

    const float* V = g_V + (size_t)bh * Dd * Nn;
    const float* P = g_S + (size_t)bh * Nn * Nn;

    float acc[2][8][4];
#pragma unroll
    for (int i = 0; i < 2; i++)
#pragma unroll
        for (int j = 0; j < 8; j++)
#pragma unroll
            for (int k = 0; k < 4; k++) acc[i][j][k] = 0.f;

    float4 va[2], vb[2];
    load_128x16(V, Nn, d0, 0, t, va);
    load_128x16(P, Nn, i0, 0, t, vb);
    store_128x16(As[0], t, va);
    store_128x16(Bs[0], t, vb);

    const int KT = Nn / 16;
    for (int kt = 0; kt < KT; kt++) {
        __syncthreads();
        int cur = kt & 1;
        if (kt + 1 < KT) {
            load_128x16(V, Nn, d0, (kt + 1) * 16, t, va);
            load_128x16(P, Nn, i0, (kt + 1) * 16, t, vb);
        }
        compute_ktile<true, true>(As[cur], Bs[cur], acc, lane, wm, wn);
        if (kt + 1 < KT) {
            store_128x16(As[cur ^ 1], t, va);
            store_128x16(Bs[cur ^ 1], t, vb);
        }
    }

    const float g = gamma[h];
    const float inv = 1.f / (1.f + g);

#pragma unroll
    for (int fm = 0; fm < 2; fm++) {
        const int d = d0 + wm * 32 + fm * 16 + (lane >> 2);
#pragma unroll
        for (int fn = 0; fn < 8; fn++) {
            const int i = i0 + wn * 64 + fn * 8 + (lane & 3) * 2;
            const float2 yp0 = *reinterpret_cast<const float2*>(
                &g_YP[((size_t)b * Cc + d) * Nn + i]);
            const float2 yp1 = *reinterpret_cast<const float2*>(
                &g_YP[((size_t)b * Cc + d + 8) * Nn + i]);
            float* p0 = out + ((size_t)b * HD + (size_t)h * Dd + d) * Nn + i;
            float* p1 = out + ((size_t)b * HD + (size_t)h * Dd + d + 8) * Nn + i;
            *reinterpret_cast<float2*>(p0) =
                make_float2((g * acc[fm][fn][0] + yp0.x) * inv,
                            (g * acc[fm][fn][1] + yp0.y) * inv);
            *reinterpret_cast<float2*>(p1) =
                make_float2((g * acc[fm][fn][2] + yp1.x) * inv,
                            (g * acc[fm][fn][3] + yp1.y) * inv);
        }
    }
}

// ---------------------------------------------------------------------------
extern "C" void kernel_launch(void* const* d_in, const int* in_sizes, int n_in,
                              void* d_out, int out_size) {
    const float* x     = (const float*)d_in[0];
    const float* y     = (const float*)d_in[1];
    const float* Wq    = (const float*)d_in[2];
    const float* bq    = (const float*)d_in[3];
    const float* Wk    = (const float*)d_in[4];
    const float* bk    = (const float*)d_in[5];
    const float* Wv    = (const float*)d_in[6];
    const float* bv    = (const float*)d_in[7];
    const float* Wp    = (const float*)d_in[8];
    const float* gamma = (const float*)d_in[9];
    float* out = (float*)d_out;

    dim3 blk(256);

    proj_t<<<dim3(Nn / 128, HD / 128, Bn), blk>>>(Wq, bq, x, HD, 0);
    proj_t<<<dim3(Nn / 128, HD / 128, Bn), blk>>>(Wk, bk, x, HD, 1);
    proj_t<<<dim3(Nn / 128, HD / 128, Bn), blk>>>(Wv, bv, y, HD, 2);
    proj_t<<<dim3(Nn / 128, Cc / 128, Bn), blk>>>(Wp, nullptr, y, Cc, 3);

    qk_t<<<dim3(Nn / 128, Nn / 128, Bn * Hh), blk>>>();
    softmax_kernel<<<Bn * Hh * Nn, 256>>>();
    av_t<<<dim3(Nn / 128, Dd / 128, Bn * Hh), blk>>>(gamma, out);
}